// round 1
// baseline (speedup 1.0000x reference)
#include <cuda_runtime.h>
#include <math.h>

// Problem constants
#define NB    8
#define NA    3
#define NH    160
#define NW    160
#define NCLS  80
#define NLOC  (NA*NH*NW)          // 76800 locations per batch
#define NGT   32
#define STRIDE_F 8.0f

// Output layout (all float32, concatenated in reference tuple order)
#define OFF_PBBOX  0                          // NB*NLOC*4 = 2457600
#define OFF_CLSIDX (NB*NLOC*4)                // 2457600
#define OFF_SCORE  (NB*NLOC*4 + NB*NLOC)      // 3072000
#define OFF_LOSS   (NB*NLOC*4 + 2*NB*NLOC)    // 3686400

__device__ double g_loss_acc;

__constant__ float c_anchors[9][2] = {
    {10.f,13.f},{16.f,30.f},{33.f,23.f},{30.f,61.f},{62.f,45.f},
    {59.f,119.f},{116.f,90.f},{156.f,198.f},{373.f,326.f}};

__device__ __forceinline__ float sigmoidf_(float x) {
    return 1.0f / (1.0f + expf(-x));
}
__device__ __forceinline__ float bce_(float x, float t) {
    return fmaxf(x, 0.0f) - x * t + log1pf(expf(-fabsf(x)));
}

__global__ void init_kernel() { g_loss_acc = 0.0; }

__global__ void fin_kernel(float* __restrict__ out) {
    out[OFF_LOSS] = (float)(g_loss_acc * (1.0 / (double)NB));
}

// ---------------------------------------------------------------------------
// Main kernel: one WARP per (b, n) location.
//  - lanes stream the 80 class logits (fully coalesced) -> warp max/argmax
//  - lane 0 decodes p_bbox, broadcasts via shuffle
//  - lane l computes IoU(p_bbox, gt[l]) -> warp max -> tconf -> bce(conf)
// Block = 256 threads = 8 warps = 8 consecutive locations (same batch;
// 9600 blocks per batch, batches never straddle a block).
// ---------------------------------------------------------------------------
__global__ __launch_bounds__(256) void main_kernel(
    const float* __restrict__ t_bbox,
    const float* __restrict__ conf,
    const float* __restrict__ cls,
    const float* __restrict__ gt,
    const unsigned char* __restrict__ gt_mask,
    float* __restrict__ out)
{
    __shared__ float4 s_gt[NGT];
    __shared__ int    s_msk[NGT];
    __shared__ float  s_part[8];

    const int b     = blockIdx.x / 9600;
    const int nbase = (blockIdx.x % 9600) * 8;
    const int tid   = threadIdx.x;
    const int warp  = tid >> 5;
    const int lane  = tid & 31;

    if (tid < NGT) {
        s_gt[tid]  = reinterpret_cast<const float4*>(gt)[b * NGT + tid];
        s_msk[tid] = gt_mask[b * NGT + tid];
    }
    __syncthreads();

    const int  n   = nbase + warp;
    const long loc = (long)b * NLOC + n;

    // --- lane 0: decode p_bbox, load conf logit ---
    float px = 0.f, py = 0.f, pw = 0.f, ph = 0.f, conf_logit = 0.f;
    if (lane == 0) {
        float4 t = reinterpret_cast<const float4*>(t_bbox)[loc];
        int a   = n / (NH * NW);
        int rem = n % (NH * NW);
        int j   = rem / NW;
        int i   = rem % NW;
        float sx = sigmoidf_(t.x), sy = sigmoidf_(t.y);
        float sw = sigmoidf_(t.z), sh = sigmoidf_(t.w);
        px = (sx * 2.0f - 0.5f + (float)i) * STRIDE_F;
        py = (sy * 2.0f - 0.5f + (float)j) * STRIDE_F;
        float tw = sw * 2.0f, th = sh * 2.0f;
        pw = tw * tw * c_anchors[a][0];
        ph = th * th * c_anchors[a][1];
        reinterpret_cast<float4*>(out + OFF_PBBOX)[loc] = make_float4(px, py, pw, ph);
        conf_logit = conf[loc];
    }
    const unsigned FULL = 0xffffffffu;
    px = __shfl_sync(FULL, px, 0);
    py = __shfl_sync(FULL, py, 0);
    pw = __shfl_sync(FULL, pw, 0);
    ph = __shfl_sync(FULL, ph, 0);

    // --- class max/argmax: lanes cover classes {l, l+32, l+64} ---
    const float* cp = cls + loc * NCLS;
    float v0 = cp[lane];
    float v1 = cp[lane + 32];
    float mv; int mi;
    if (v1 > v0) { mv = v1; mi = lane + 32; } else { mv = v0; mi = lane; }
    if (lane < 16) {
        float v2 = cp[lane + 64];
        if (v2 > mv) { mv = v2; mi = lane + 64; }
    }
    #pragma unroll
    for (int off = 16; off; off >>= 1) {
        float ov = __shfl_down_sync(FULL, mv, off);
        int   oi = __shfl_down_sync(FULL, mi, off);
        if (ov > mv || (ov == mv && oi < mi)) { mv = ov; mi = oi; }
    }

    // --- IoU vs 32 GT boxes: one per lane ---
    float iou = -1.0f;
    {
        float4 g = s_gt[lane];
        if (s_msk[lane]) {
            float ax1 = px - pw * 0.5f, ax2 = px + pw * 0.5f;
            float ay1 = py - ph * 0.5f, ay2 = py + ph * 0.5f;
            float bx1 = g.x - g.z * 0.5f, bx2 = g.x + g.z * 0.5f;
            float by1 = g.y - g.w * 0.5f, by2 = g.y + g.w * 0.5f;
            float iw = fmaxf(fminf(ax2, bx2) - fmaxf(ax1, bx1), 0.0f);
            float ih = fmaxf(fminf(ay2, by2) - fmaxf(ay1, by1), 0.0f);
            float inter = iw * ih;
            float uni = (ax2 - ax1) * (ay2 - ay1) + (bx2 - bx1) * (by2 - by1) - inter;
            iou = inter / (uni + 1e-16f);
        }
    }
    #pragma unroll
    for (int off = 16; off; off >>= 1)
        iou = fmaxf(iou, __shfl_down_sync(FULL, iou, off));

    // --- lane 0: outputs + conf loss contribution ---
    if (lane == 0) {
        float tconf = fmaxf(iou, 0.0f);   // -1 only when no valid GT -> 0
        float lconf = bce_(conf_logit, tconf);
        out[OFF_CLSIDX + loc] = (float)mi;
        out[OFF_SCORE  + loc] = sigmoidf_(conf_logit) * sigmoidf_(mv);
        s_part[warp] = lconf;
    }
    __syncthreads();
    if (tid == 0) {
        float s = 0.0f;
        #pragma unroll
        for (int k = 0; k < 8; k++) s += s_part[k];
        atomicAdd(&g_loss_acc, (double)s);
    }
}

// ---------------------------------------------------------------------------
// Per-GT kernel: 256 GTs, one thread each (anchor match + xy/wh/cls losses)
// ---------------------------------------------------------------------------
__global__ __launch_bounds__(256) void gt_kernel(
    const float* __restrict__ t_bbox,
    const float* __restrict__ cls,
    const float* __restrict__ gt,
    const int*   __restrict__ gt_cls,
    const unsigned char* __restrict__ gt_mask)
{
    int tid = threadIdx.x;
    if (tid >= NB * NGT) return;
    int b = tid / NGT;
    int g = tid % NGT;
    if (!gt_mask[b * NGT + g]) return;

    float4 gb = reinterpret_cast<const float4*>(gt)[b * NGT + g];
    float gw = gb.z, gh = gb.w;

    // anchor argmax over all 9 anchors (first-max tie-break)
    int best = 0; float bestr = -1.0f;
    #pragma unroll
    for (int a = 0; a < 9; a++) {
        float aw = c_anchors[a][0], ah = c_anchors[a][1];
        float inter = fminf(gw, aw) * fminf(gh, ah);
        float uni = gw * gh + aw * ah - inter;
        float r = inter / (uni + 1e-16f);
        if (r > bestr) { bestr = r; best = a; }
    }
    if (best >= NA) return;  // not matched to this level's anchors {0,1,2}
    int ta = best;

    float cxs = gb.x * (1.0f / STRIDE_F);
    float cys = gb.y * (1.0f / STRIDE_F);
    int ti = min(max((int)cxs, 0), NW - 1);
    int tj = min(max((int)cys, 0), NH - 1);

    long cell = ((long)(b * NA + ta) * NH + tj) * NW + ti;
    float4 tb = reinterpret_cast<const float4*>(t_bbox)[cell];

    float tgx = (fmodf(cxs, 1.0f) + 0.5f) * 0.5f;
    float tgy = (fmodf(cys, 1.0f) + 0.5f) * 0.5f;
    float tgw = sqrtf(gw / c_anchors[ta][0]) * 0.5f;
    float tgh = sqrtf(gh / c_anchors[ta][1]) * 0.5f;

    float lxy = bce_(tb.x, tgx) + bce_(tb.y, tgy);
    float lwh = bce_(tb.z, tgw) + bce_(tb.w, tgh);

    const float* cl = cls + cell * NCLS;
    int tc = gt_cls[b * NGT + g];
    float lcls = 0.0f;
    #pragma unroll 8
    for (int c = 0; c < NCLS; c++)
        lcls += bce_(cl[c], (c == tc) ? 1.0f : 0.0f);
    lcls *= (1.0f / NCLS);

    atomicAdd(&g_loss_acc, (double)(lxy + lwh + lcls));
}

extern "C" void kernel_launch(void* const* d_in, const int* in_sizes, int n_in,
                              void* d_out, int out_size)
{
    const float* t_bbox = (const float*)d_in[0];
    const float* conf   = (const float*)d_in[1];
    const float* cls    = (const float*)d_in[2];
    const float* gt     = (const float*)d_in[3];
    const int*   gtc    = (const int*)d_in[4];
    const unsigned char* msk = (const unsigned char*)d_in[5];
    float* out = (float*)d_out;

    init_kernel<<<1, 1>>>();
    main_kernel<<<NB * 9600, 256>>>(t_bbox, conf, cls, gt, msk, out);
    gt_kernel<<<1, 256>>>(t_bbox, cls, gt, gtc, msk);
    fin_kernel<<<1, 1>>>(out);
}

// round 2
// speedup vs baseline: 2.6654x; 2.6654x over previous
#include <cuda_runtime.h>
#include <math.h>

#define NB    8
#define NA    3
#define NH    160
#define NW    160
#define NCLS  80
#define NLOC  (NA*NH*NW)          // 76800 per batch
#define NGT   32
#define STRIDE_F 8.0f

#define TILE   128                 // locations per block
#define NBLK   (NB*NLOC/TILE)      // 4800
#define BLK_PER_B (NLOC/TILE)      // 600

#define OFF_PBBOX  0
#define OFF_CLSIDX (NB*NLOC*4)
#define OFF_SCORE  (NB*NLOC*4 + NB*NLOC)
#define OFF_LOSS   (NB*NLOC*4 + 2*NB*NLOC)

__device__ float g_part[NBLK];

__constant__ float c_anchors[9][2] = {
    {10.f,13.f},{16.f,30.f},{33.f,23.f},{30.f,61.f},{62.f,45.f},
    {59.f,119.f},{116.f,90.f},{156.f,198.f},{373.f,326.f}};

__device__ __forceinline__ float sigmoidf_(float x) {
    return 1.0f / (1.0f + expf(-x));
}
__device__ __forceinline__ float bce_(float x, float t) {
    return fmaxf(x, 0.0f) - x * t + log1pf(expf(-fabsf(x)));
}

// ---------------------------------------------------------------------------
// Main kernel: block = 256 threads handles TILE=128 consecutive locations.
// Phase 1: coalesced float4 load of 128x80 cls logits -> SMEM, layout
//          [class_group 0..19][chunk 0..128] of float4, chunk-stride 129
//          (129 mod 8 == 1 => STS.128 and LDS.128 conflict-free).
// Phase 2: 2 threads per location scan 40 classes each (10 LDS.128),
//          pair-combine via shfl_xor(1).
// Phase 3: decode bbox (both threads, same data), IoU vs 16 GTs each,
//          pair max via shfl_xor(1), even thread writes outputs + conf bce.
// ---------------------------------------------------------------------------
__global__ __launch_bounds__(256) void main_kernel(
    const float* __restrict__ t_bbox,
    const float* __restrict__ conf,
    const float* __restrict__ cls,
    const float* __restrict__ gt,
    const unsigned char* __restrict__ gt_mask,
    float* __restrict__ out)
{
    __shared__ float4 s_cls[20 * 129];       // 41280 B
    __shared__ float  s_bx1[NGT], s_bx2[NGT], s_by1[NGT], s_by2[NGT];
    __shared__ float  s_areaB[NGT];
    __shared__ int    s_valid[NGT];
    __shared__ float  s_warp[8];

    const int tid   = threadIdx.x;
    const int b     = blockIdx.x / BLK_PER_B;
    const int nbase = (blockIdx.x % BLK_PER_B) * TILE;

    // --- GT staging (32 threads) ---
    if (tid < NGT) {
        float4 g = reinterpret_cast<const float4*>(gt)[b * NGT + tid];
        s_bx1[tid] = g.x - g.z * 0.5f;
        s_bx2[tid] = g.x + g.z * 0.5f;
        s_by1[tid] = g.y - g.w * 0.5f;
        s_by2[tid] = g.y + g.w * 0.5f;
        s_areaB[tid] = g.z * g.w;
        s_valid[tid] = gt_mask[b * NGT + tid];
    }

    // --- Phase 1: stage cls tile (128 locs x 80 cls = 2560 float4) ---
    {
        const float4* src = reinterpret_cast<const float4*>(
            cls + ((long)b * NLOC + nbase) * NCLS);
        #pragma unroll
        for (int k = 0; k < 10; k++) {
            int fi = k * 256 + tid;          // float4 index in tile
            float4 v = src[fi];
            int F   = fi * 4;                // float index
            int loc = F / NCLS;
            int cg  = (F % NCLS) >> 2;       // class group 0..19
            s_cls[cg * 129 + loc] = v;
        }
    }
    __syncthreads();

    // --- Phase 2: class max/argmax, 2 threads per location ---
    const int loc = tid >> 1;
    const int h   = tid & 1;
    float mv = -1e30f; int mi = 0;
    {
        #pragma unroll
        for (int k = 0; k < 10; k++) {
            int cg = h * 10 + k;
            float4 v = s_cls[cg * 129 + loc];
            int cbase = cg * 4;
            if (v.x > mv) { mv = v.x; mi = cbase;     }
            if (v.y > mv) { mv = v.y; mi = cbase + 1; }
            if (v.z > mv) { mv = v.z; mi = cbase + 2; }
            if (v.w > mv) { mv = v.w; mi = cbase + 3; }
        }
        const unsigned FULL = 0xffffffffu;
        float ov = __shfl_xor_sync(FULL, mv, 1);
        int   oi = __shfl_xor_sync(FULL, mi, 1);
        if (ov > mv || (ov == mv && oi < mi)) { mv = ov; mi = oi; }
    }

    // --- Phase 3: decode + IoU ---
    const int  n   = nbase + loc;
    const long gloc = (long)b * NLOC + n;

    float4 t = reinterpret_cast<const float4*>(t_bbox)[gloc];
    int a   = n / (NH * NW);
    int rem = n % (NH * NW);
    int j   = rem / NW;
    int i   = rem % NW;
    float sx = sigmoidf_(t.x), sy = sigmoidf_(t.y);
    float sw = sigmoidf_(t.z), sh = sigmoidf_(t.w);
    float px = (sx * 2.0f - 0.5f + (float)i) * STRIDE_F;
    float py = (sy * 2.0f - 0.5f + (float)j) * STRIDE_F;
    float tw = sw * 2.0f, th = sh * 2.0f;
    float pw = tw * tw * c_anchors[a][0];
    float ph = th * th * c_anchors[a][1];

    float ax1 = px - pw * 0.5f, ax2 = px + pw * 0.5f;
    float ay1 = py - ph * 0.5f, ay2 = py + ph * 0.5f;
    float areaA = (ax2 - ax1) * (ay2 - ay1);

    float iou = -1.0f;
    #pragma unroll
    for (int k = 0; k < 16; k++) {
        int g = h * 16 + k;
        float iw = fmaxf(fminf(ax2, s_bx2[g]) - fmaxf(ax1, s_bx1[g]), 0.0f);
        float ih = fmaxf(fminf(ay2, s_by2[g]) - fmaxf(ay1, s_by1[g]), 0.0f);
        float inter = iw * ih;
        float uni = areaA + s_areaB[g] - inter;
        float v = inter / (uni + 1e-16f);
        v = s_valid[g] ? v : -1.0f;
        iou = fmaxf(iou, v);
    }
    {
        const unsigned FULL = 0xffffffffu;
        iou = fmaxf(iou, __shfl_xor_sync(FULL, iou, 1));
    }

    // --- even thread: outputs + conf loss contribution ---
    float lconf = 0.0f;
    if (h == 0) {
        float conf_logit = conf[gloc];
        float tconf = fmaxf(iou, 0.0f);
        lconf = bce_(conf_logit, tconf);
        reinterpret_cast<float4*>(out + OFF_PBBOX)[gloc] =
            make_float4(px, py, pw, ph);
        out[OFF_CLSIDX + gloc] = (float)mi;
        out[OFF_SCORE  + gloc] = sigmoidf_(conf_logit) * sigmoidf_(mv);
    }

    // --- deterministic block reduction of lconf ---
    {
        const unsigned FULL = 0xffffffffu;
        float s = lconf;
        #pragma unroll
        for (int off = 16; off; off >>= 1)
            s += __shfl_down_sync(FULL, s, off);
        if ((tid & 31) == 0) s_warp[tid >> 5] = s;
    }
    __syncthreads();
    if (tid == 0) {
        float s = 0.0f;
        #pragma unroll
        for (int w = 0; w < 8; w++) s += s_warp[w];
        g_part[blockIdx.x] = s;
    }
}

// ---------------------------------------------------------------------------
// fin kernel: per-GT losses (256 threads, one GT each) + deterministic
// reduction of all block partials -> final scalar loss.
// ---------------------------------------------------------------------------
__global__ __launch_bounds__(256) void fin_kernel(
    const float* __restrict__ t_bbox,
    const float* __restrict__ cls,
    const float* __restrict__ gt,
    const int*   __restrict__ gt_cls,
    const unsigned char* __restrict__ gt_mask,
    float* __restrict__ out)
{
    __shared__ double s_red[256];
    const int tid = threadIdx.x;

    // per-GT loss
    double gt_loss = 0.0;
    {
        int b = tid / NGT;
        int g = tid % NGT;
        if (gt_mask[b * NGT + g]) {
            float4 gb = reinterpret_cast<const float4*>(gt)[b * NGT + g];
            float gw = gb.z, gh = gb.w;
            int best = 0; float bestr = -1.0f;
            #pragma unroll
            for (int a = 0; a < 9; a++) {
                float aw = c_anchors[a][0], ah = c_anchors[a][1];
                float inter = fminf(gw, aw) * fminf(gh, ah);
                float uni = gw * gh + aw * ah - inter;
                float r = inter / (uni + 1e-16f);
                if (r > bestr) { bestr = r; best = a; }
            }
            if (best < NA) {
                int ta = best;
                float cxs = gb.x * (1.0f / STRIDE_F);
                float cys = gb.y * (1.0f / STRIDE_F);
                int ti = min(max((int)cxs, 0), NW - 1);
                int tj = min(max((int)cys, 0), NH - 1);
                long cell = ((long)(b * NA + ta) * NH + tj) * NW + ti;
                float4 tb = reinterpret_cast<const float4*>(t_bbox)[cell];
                float tgx = (fmodf(cxs, 1.0f) + 0.5f) * 0.5f;
                float tgy = (fmodf(cys, 1.0f) + 0.5f) * 0.5f;
                float tgw = sqrtf(gw / c_anchors[ta][0]) * 0.5f;
                float tgh = sqrtf(gh / c_anchors[ta][1]) * 0.5f;
                float lxy = bce_(tb.x, tgx) + bce_(tb.y, tgy);
                float lwh = bce_(tb.z, tgw) + bce_(tb.w, tgh);
                const float* cl = cls + cell * NCLS;
                int tc = gt_cls[b * NGT + g];
                float lcls = 0.0f;
                #pragma unroll 8
                for (int c = 0; c < NCLS; c++)
                    lcls += bce_(cl[c], (c == tc) ? 1.0f : 0.0f);
                lcls *= (1.0f / NCLS);
                gt_loss = (double)(lxy + lwh + lcls);
            }
        }
    }

    // sum block partials (fixed order => deterministic)
    double acc = gt_loss;
    for (int idx = tid; idx < NBLK; idx += 256)
        acc += (double)g_part[idx];

    s_red[tid] = acc;
    __syncthreads();
    #pragma unroll
    for (int off = 128; off; off >>= 1) {
        if (tid < off) s_red[tid] += s_red[tid + off];
        __syncthreads();
    }
    if (tid == 0)
        out[OFF_LOSS] = (float)(s_red[0] * (1.0 / (double)NB));
}

extern "C" void kernel_launch(void* const* d_in, const int* in_sizes, int n_in,
                              void* d_out, int out_size)
{
    const float* t_bbox = (const float*)d_in[0];
    const float* conf   = (const float*)d_in[1];
    const float* cls    = (const float*)d_in[2];
    const float* gt     = (const float*)d_in[3];
    const int*   gtc    = (const int*)d_in[4];
    const unsigned char* msk = (const unsigned char*)d_in[5];
    float* out = (float*)d_out;

    main_kernel<<<NBLK, 256>>>(t_bbox, conf, cls, gt, msk, out);
    fin_kernel<<<1, 256>>>(t_bbox, cls, gt, gtc, msk, out);
}

// round 3
// speedup vs baseline: 3.2192x; 1.2078x over previous
#include <cuda_runtime.h>
#include <math.h>

#define NB    8
#define NA    3
#define NH    160
#define NW    160
#define NCLS  80
#define NLOC  (NA*NH*NW)          // 76800 per batch
#define NGT   32
#define STRIDE_F 8.0f

#define TILE   128                 // locations per block
#define NBLK   (NB*NLOC/TILE)      // 4800
#define BLK_PER_B (NLOC/TILE)      // 600
#define CSTR   133                 // smem chunk stride (conflict-free, see notes)

#define OFF_PBBOX  0
#define OFF_CLSIDX (NB*NLOC*4)
#define OFF_SCORE  (NB*NLOC*4 + NB*NLOC)
#define OFF_LOSS   (NB*NLOC*4 + 2*NB*NLOC)

__device__ double       g_loss_acc;
__device__ unsigned int g_done_count;

__constant__ float c_anchors[9][2] = {
    {10.f,13.f},{16.f,30.f},{33.f,23.f},{30.f,61.f},{62.f,45.f},
    {59.f,119.f},{116.f,90.f},{156.f,198.f},{373.f,326.f}};

__device__ __forceinline__ float sigmoidf_(float x) {
    return 1.0f / (1.0f + expf(-x));
}
__device__ __forceinline__ float bce_(float x, float t) {
    return fmaxf(x, 0.0f) - x * t + log1pf(expf(-fabsf(x)));
}

// ---------------------------------------------------------------------------
// Single fused kernel. Block = 256 threads -> TILE=128 consecutive locations.
//  P1: coalesced float4 stream of 128x80 cls logits -> SMEM transpose
//      layout [cg][chunk] float4, chunk-stride CSTR=133 (STS.128 lane windows
//      step 20 banks -> disjoint; LDS.128 with cg=2k+h -> disjoint).
//  P2: 2 threads/location scan 40 classes each (10 LDS.128), shfl_xor(1).
//  P3: decode bbox, IoU vs 16 GTs each (invalid GTs = degenerate -> iou 0),
//      shfl_xor(1) max, even thread writes outputs + conf bce.
//  Block 0 threads additionally compute the 256 per-GT losses.
//  Loss: block reduce -> atomicAdd(double) -> last block writes scalar.
// ---------------------------------------------------------------------------
__global__ __launch_bounds__(256) void main_kernel(
    const float* __restrict__ t_bbox,
    const float* __restrict__ conf,
    const float* __restrict__ cls,
    const float* __restrict__ gt,
    const int*   __restrict__ gt_cls,
    const unsigned char* __restrict__ gt_mask,
    float* __restrict__ out)
{
    __shared__ float4 s_cls[20 * CSTR];          // 42560 B
    __shared__ float4 s_gtc[NGT + 2];            // corners, pad g + g/16
    __shared__ float  s_areaB[NGT];
    __shared__ float  s_warp[8];

    const int tid   = threadIdx.x;
    const int b     = blockIdx.x / BLK_PER_B;
    const int nbase = (blockIdx.x % BLK_PER_B) * TILE;

    // --- GT staging ---
    if (tid < NGT) {
        float4 g = reinterpret_cast<const float4*>(gt)[b * NGT + tid];
        int valid = gt_mask[b * NGT + tid];
        int si = tid + (tid >> 4);
        if (valid) {
            s_gtc[si] = make_float4(g.x - g.z * 0.5f, g.y - g.w * 0.5f,
                                    g.x + g.z * 0.5f, g.y + g.w * 0.5f);
            s_areaB[tid] = g.z * g.w;
        } else {
            // degenerate far box: iw,ih clamp to 0 -> iou = 0 (correct: tconf
            // is max over valid ious which are >=0, or 0 when no GT at all)
            s_gtc[si] = make_float4(-3e8f, -3e8f, -3e8f, -3e8f);
            s_areaB[tid] = 0.0f;
        }
    }

    // --- P1: stage cls tile (128 locs x 80 cls = 2560 float4) ---
    {
        const float4* src = reinterpret_cast<const float4*>(
            cls + ((long)b * NLOC + nbase) * NCLS);
        #pragma unroll
        for (int k = 0; k < 10; k++) {
            int fi = k * 256 + tid;              // float4 index in tile
            float4 v = __ldcs(src + fi);
            s_cls[(fi % 20) * CSTR + fi / 20] = v;
        }
    }
    __syncthreads();

    // --- P2: class max/argmax, 2 threads per location, cg = 2k + h ---
    const int loc = tid >> 1;
    const int h   = tid & 1;
    const unsigned FULL = 0xffffffffu;
    float mv = -1e30f; int mi = 0;
    {
        #pragma unroll
        for (int k = 0; k < 10; k++) {
            int cg = 2 * k + h;
            float4 v = s_cls[cg * CSTR + loc];
            int cbase = cg * 4;
            if (v.x > mv) { mv = v.x; mi = cbase;     }
            if (v.y > mv) { mv = v.y; mi = cbase + 1; }
            if (v.z > mv) { mv = v.z; mi = cbase + 2; }
            if (v.w > mv) { mv = v.w; mi = cbase + 3; }
        }
        float ov = __shfl_xor_sync(FULL, mv, 1);
        int   oi = __shfl_xor_sync(FULL, mi, 1);
        if (ov > mv || (ov == mv && oi < mi)) { mv = ov; mi = oi; }
    }

    // --- P3: decode + IoU ---
    const int  n    = nbase + loc;
    const long gloc = (long)b * NLOC + n;

    float4 t = reinterpret_cast<const float4*>(t_bbox)[gloc];
    int a   = n / (NH * NW);
    int rem = n % (NH * NW);
    int j   = rem / NW;
    int i   = rem % NW;
    float sx = sigmoidf_(t.x), sy = sigmoidf_(t.y);
    float sw = sigmoidf_(t.z), sh = sigmoidf_(t.w);
    float px = (sx * 2.0f - 0.5f + (float)i) * STRIDE_F;
    float py = (sy * 2.0f - 0.5f + (float)j) * STRIDE_F;
    float tw = sw * 2.0f, th = sh * 2.0f;
    float pw = tw * tw * c_anchors[a][0];
    float ph = th * th * c_anchors[a][1];

    float ax1 = px - pw * 0.5f, ax2 = px + pw * 0.5f;
    float ay1 = py - ph * 0.5f, ay2 = py + ph * 0.5f;
    float areaA = (ax2 - ax1) * (ay2 - ay1);

    float iou = 0.0f;
    #pragma unroll
    for (int k = 0; k < 16; k++) {
        int g = h * 16 + k;
        float4 c = s_gtc[g + (g >> 4)];
        float iw = fmaxf(fminf(ax2, c.z) - fmaxf(ax1, c.x), 0.0f);
        float ih = fmaxf(fminf(ay2, c.w) - fmaxf(ay1, c.y), 0.0f);
        float inter = iw * ih;
        float uni = areaA + s_areaB[g] - inter;
        iou = fmaxf(iou, inter / (uni + 1e-16f));
    }
    iou = fmaxf(iou, __shfl_xor_sync(FULL, iou, 1));

    // --- even thread: outputs + conf loss contribution ---
    float lsum = 0.0f;
    if (h == 0) {
        float conf_logit = conf[gloc];
        lsum = bce_(conf_logit, iou);
        reinterpret_cast<float4*>(out + OFF_PBBOX)[gloc] =
            make_float4(px, py, pw, ph);
        out[OFF_CLSIDX + gloc] = (float)mi;
        out[OFF_SCORE  + gloc] = sigmoidf_(conf_logit) * sigmoidf_(mv);
    }

    // --- block 0 additionally: per-GT losses, one GT per thread ---
    if (blockIdx.x == 0) {
        int gb = tid / NGT;
        int gg = tid % NGT;
        if (gt_mask[gb * NGT + gg]) {
            float4 gbx = reinterpret_cast<const float4*>(gt)[gb * NGT + gg];
            float gw = gbx.z, gh = gbx.w;
            int best = 0; float bestr = -1.0f;
            #pragma unroll
            for (int aa = 0; aa < 9; aa++) {
                float aw = c_anchors[aa][0], ah = c_anchors[aa][1];
                float inter = fminf(gw, aw) * fminf(gh, ah);
                float uni = gw * gh + aw * ah - inter;
                float r = inter / (uni + 1e-16f);
                if (r > bestr) { bestr = r; best = aa; }
            }
            if (best < NA) {
                int ta = best;
                float cxs = gbx.x * (1.0f / STRIDE_F);
                float cys = gbx.y * (1.0f / STRIDE_F);
                int ti = min(max((int)cxs, 0), NW - 1);
                int tj = min(max((int)cys, 0), NH - 1);
                long cell = ((long)(gb * NA + ta) * NH + tj) * NW + ti;
                float4 tb = reinterpret_cast<const float4*>(t_bbox)[cell];
                float tgx = (fmodf(cxs, 1.0f) + 0.5f) * 0.5f;
                float tgy = (fmodf(cys, 1.0f) + 0.5f) * 0.5f;
                float tgw = sqrtf(gw / c_anchors[ta][0]) * 0.5f;
                float tgh = sqrtf(gh / c_anchors[ta][1]) * 0.5f;
                lsum += bce_(tb.x, tgx) + bce_(tb.y, tgy);
                lsum += bce_(tb.z, tgw) + bce_(tb.w, tgh);
                const float* cl = cls + cell * NCLS;
                int tc = gt_cls[gb * NGT + gg];
                float lcls = 0.0f;
                #pragma unroll 8
                for (int c = 0; c < NCLS; c++)
                    lcls += bce_(cl[c], (c == tc) ? 1.0f : 0.0f);
                lsum += lcls * (1.0f / NCLS);
            }
        }
    }

    // --- block reduction -> global double accumulator ---
    #pragma unroll
    for (int off = 16; off; off >>= 1)
        lsum += __shfl_down_sync(FULL, lsum, off);
    if ((tid & 31) == 0) s_warp[tid >> 5] = lsum;
    __syncthreads();
    if (tid == 0) {
        float s = 0.0f;
        #pragma unroll
        for (int w = 0; w < 8; w++) s += s_warp[w];
        atomicAdd(&g_loss_acc, (double)s);
        __threadfence();
        unsigned int done = atomicAdd(&g_done_count, 1u);
        if (done == NBLK - 1) {
            double total = atomicAdd(&g_loss_acc, 0.0);  // read full sum
            out[OFF_LOSS] = (float)(total * (1.0 / (double)NB));
            g_loss_acc   = 0.0;      // reset for next graph replay
            g_done_count = 0u;
        }
    }
}

extern "C" void kernel_launch(void* const* d_in, const int* in_sizes, int n_in,
                              void* d_out, int out_size)
{
    const float* t_bbox = (const float*)d_in[0];
    const float* conf   = (const float*)d_in[1];
    const float* cls    = (const float*)d_in[2];
    const float* gt     = (const float*)d_in[3];
    const int*   gtc    = (const int*)d_in[4];
    const unsigned char* msk = (const unsigned char*)d_in[5];
    float* out = (float*)d_out;

    main_kernel<<<NBLK, 256>>>(t_bbox, conf, cls, gt, gtc, msk, out);
}

// round 6
// speedup vs baseline: 4.1057x; 1.2754x over previous
#include <cuda_runtime.h>
#include <math.h>

#define NB    8
#define NA    3
#define NH    160
#define NW    160
#define NCLS  80
#define NLOC  (NA*NH*NW)          // 76800 per batch
#define NGT   32
#define STRIDE_F 8.0f

#define TILE   128                 // locations per block
#define NBLK   (NB*NLOC/TILE)      // 4800
#define BLK_PER_B (NLOC/TILE)      // 600
#define ROWF4  21                  // float4 per location row (20 + 1 pad)

#define OFF_PBBOX  0
#define OFF_CLSIDX (NB*NLOC*4)
#define OFF_SCORE  (NB*NLOC*4 + NB*NLOC)
#define OFF_LOSS   (NB*NLOC*4 + 2*NB*NLOC)

__device__ double       g_loss_acc;
__device__ unsigned int g_done_count;

__constant__ float c_anchors[9][2] = {
    {10.f,13.f},{16.f,30.f},{33.f,23.f},{30.f,61.f},{62.f,45.f},
    {59.f,119.f},{116.f,90.f},{156.f,198.f},{373.f,326.f}};

__device__ __forceinline__ float sigmoidf_(float x) {
    return __fdividef(1.0f, 1.0f + __expf(-x));
}
__device__ __forceinline__ float bce_(float x, float t) {
    return fmaxf(x, 0.0f) - x * t + log1pf(__expf(-fabsf(x)));
}

// ---------------------------------------------------------------------------
// Single fused kernel. Block = 256 threads -> TILE=128 consecutive locations.
//  P1: coalesced float4 stream of 128x80 cls -> SMEM layout [loc][cg] with
//      row pad 21 float4 (LDS.128 conflict-free; store addr = fi + fi/20).
//  P2: 2 threads/loc, 10 groups each (cg = 2k+h): group-max (3 FMNMX) +
//      group tracking, then 1 re-read to recover the in-group index.
//  P3: decode bbox, IoU vs 16 GTs each (fast div; invalid GT = degenerate),
//      shfl_xor(1) max; even thread writes outputs + conf bce.
//  Block 0 threads also compute 256 per-GT losses.
//  Loss: block reduce -> atomicAdd(double) -> last block writes scalar.
// ---------------------------------------------------------------------------
__global__ __launch_bounds__(256) void main_kernel(
    const float* __restrict__ t_bbox,
    const float* __restrict__ conf,
    const float* __restrict__ cls,
    const float* __restrict__ gt,
    const int*   __restrict__ gt_cls,
    const unsigned char* __restrict__ gt_mask,
    float* __restrict__ out)
{
    __shared__ float4 s_cls[TILE * ROWF4];       // 43008 B
    __shared__ float4 s_gtc[NGT + 2];            // corners, pad g + g/16
    __shared__ float  s_areaB[NGT];
    __shared__ float  s_warp[8];

    const int tid    = threadIdx.x;
    const int blkmod = blockIdx.x % BLK_PER_B;
    const int b      = blockIdx.x / BLK_PER_B;
    const int nbase  = blkmod * TILE;

    // --- GT staging ---
    if (tid < NGT) {
        float4 g = reinterpret_cast<const float4*>(gt)[b * NGT + tid];
        int valid = gt_mask[b * NGT + tid];
        int si = tid + (tid >> 4);
        if (valid) {
            s_gtc[si] = make_float4(g.x - g.z * 0.5f, g.y - g.w * 0.5f,
                                    g.x + g.z * 0.5f, g.y + g.w * 0.5f);
            s_areaB[tid] = g.z * g.w;
        } else {
            s_gtc[si] = make_float4(-3e8f, -3e8f, -3e8f, -3e8f);
            s_areaB[tid] = 0.0f;
        }
    }

    // --- P1: stage cls tile (2560 float4), layout [loc*21 + cg] ---
    {
        const float4* src = reinterpret_cast<const float4*>(cls)
                          + (b * NLOC + nbase) * 20;
        #pragma unroll
        for (int k = 0; k < 10; k++) {
            int fi = k * 256 + tid;              // float4 index in tile
            float4 v = __ldcs(src + fi);
            s_cls[fi + fi / 20] = v;             // loc*21 + cg
        }
    }
    __syncthreads();

    // --- P2: class max/argmax, 2 threads per location, cg = 2k + h ---
    const int loc  = tid >> 1;
    const int h    = tid & 1;
    const int base = loc * ROWF4;
    const unsigned FULL = 0xffffffffu;

    float gm = -1e30f; int gcg = h;
    {
        #pragma unroll
        for (int k = 0; k < 10; k++) {
            int cg = 2 * k + h;
            float4 v = s_cls[base + cg];
            float m = fmaxf(fmaxf(v.x, v.y), fmaxf(v.z, v.w));
            if (m > gm) { gm = m; gcg = cg; }
        }
    }
    // recover index within winning group (first equal wins)
    float mv = gm; int mi;
    {
        float4 v = s_cls[base + gcg];
        int r = (v.z == gm) ? 2 : 3;
        if (v.y == gm) r = 1;
        if (v.x == gm) r = 0;
        mi = gcg * 4 + r;
    }
    {
        float ov = __shfl_xor_sync(FULL, mv, 1);
        int   oi = __shfl_xor_sync(FULL, mi, 1);
        if (ov > mv || (ov == mv && oi < mi)) { mv = ov; mi = oi; }
    }

    // --- P3: decode + IoU ---
    const int n    = nbase + loc;
    const int gloc = b * NLOC + n;

    float4 t = reinterpret_cast<const float4*>(t_bbox)[gloc];
    const int a   = blkmod / 200;                       // block-uniform
    const int rem = (blkmod % 200) * TILE + loc;        // n % 25600
    const int j   = rem / NW;
    const int i   = rem - j * NW;
    float sx = sigmoidf_(t.x), sy = sigmoidf_(t.y);
    float sw = sigmoidf_(t.z), sh = sigmoidf_(t.w);
    float px = (sx * 2.0f - 0.5f + (float)i) * STRIDE_F;
    float py = (sy * 2.0f - 0.5f + (float)j) * STRIDE_F;
    float tw = sw * 2.0f, th = sh * 2.0f;
    float pw = tw * tw * c_anchors[a][0];
    float ph = th * th * c_anchors[a][1];

    float ax1 = px - pw * 0.5f, ax2 = px + pw * 0.5f;
    float ay1 = py - ph * 0.5f, ay2 = py + ph * 0.5f;
    float areaA = (ax2 - ax1) * (ay2 - ay1);

    float iou = 0.0f;
    #pragma unroll
    for (int k = 0; k < 16; k++) {
        int g = h * 16 + k;
        float4 c = s_gtc[g + (g >> 4)];
        float iw = fmaxf(fminf(ax2, c.z) - fmaxf(ax1, c.x), 0.0f);
        float ih = fmaxf(fminf(ay2, c.w) - fmaxf(ay1, c.y), 0.0f);
        float inter = iw * ih;
        float uni = areaA + s_areaB[g] - inter;
        iou = fmaxf(iou, __fdividef(inter, uni + 1e-16f));
    }
    iou = fmaxf(iou, __shfl_xor_sync(FULL, iou, 1));

    // --- even thread: outputs + conf loss contribution ---
    float lsum = 0.0f;
    if (h == 0) {
        float conf_logit = conf[gloc];
        lsum = bce_(conf_logit, iou);
        reinterpret_cast<float4*>(out + OFF_PBBOX)[gloc] =
            make_float4(px, py, pw, ph);
        out[OFF_CLSIDX + gloc] = (float)mi;
        out[OFF_SCORE  + gloc] = sigmoidf_(conf_logit) * sigmoidf_(mv);
    }

    // --- block 0 additionally: per-GT losses, one GT per thread ---
    if (blockIdx.x == 0) {
        int gb = tid / NGT;
        int gg = tid % NGT;
        if (gt_mask[gb * NGT + gg]) {
            float4 gbx = reinterpret_cast<const float4*>(gt)[gb * NGT + gg];
            float gw = gbx.z, gh = gbx.w;
            int best = 0; float bestr = -1.0f;
            #pragma unroll
            for (int aa = 0; aa < 9; aa++) {
                float aw = c_anchors[aa][0], ah = c_anchors[aa][1];
                float inter = fminf(gw, aw) * fminf(gh, ah);
                float uni = gw * gh + aw * ah - inter;
                float r = inter / (uni + 1e-16f);
                if (r > bestr) { bestr = r; best = aa; }
            }
            if (best < NA) {
                int ta = best;
                float cxs = gbx.x * (1.0f / STRIDE_F);
                float cys = gbx.y * (1.0f / STRIDE_F);
                int ti = min(max((int)cxs, 0), NW - 1);
                int tj = min(max((int)cys, 0), NH - 1);
                int cell = ((gb * NA + ta) * NH + tj) * NW + ti;
                float4 tb = reinterpret_cast<const float4*>(t_bbox)[cell];
                float tgx = (fmodf(cxs, 1.0f) + 0.5f) * 0.5f;
                float tgy = (fmodf(cys, 1.0f) + 0.5f) * 0.5f;
                float tgw = sqrtf(gw / c_anchors[ta][0]) * 0.5f;
                float tgh = sqrtf(gh / c_anchors[ta][1]) * 0.5f;
                lsum += bce_(tb.x, tgx) + bce_(tb.y, tgy);
                lsum += bce_(tb.z, tgw) + bce_(tb.w, tgh);
                const float* cl = cls + cell * NCLS;
                int tc = gt_cls[gb * NGT + gg];
                float lcls = 0.0f;
                #pragma unroll 8
                for (int c = 0; c < NCLS; c++)
                    lcls += bce_(cl[c], (c == tc) ? 1.0f : 0.0f);
                lsum += lcls * (1.0f / NCLS);
            }
        }
    }

    // --- block reduction -> global double accumulator ---
    #pragma unroll
    for (int off = 16; off; off >>= 1)
        lsum += __shfl_down_sync(FULL, lsum, off);
    if ((tid & 31) == 0) s_warp[tid >> 5] = lsum;
    __syncthreads();
    if (tid == 0) {
        float s = 0.0f;
        #pragma unroll
        for (int w = 0; w < 8; w++) s += s_warp[w];
        atomicAdd(&g_loss_acc, (double)s);
        __threadfence();
        unsigned int done = atomicAdd(&g_done_count, 1u);
        if (done == NBLK - 1) {
            double total = atomicAdd(&g_loss_acc, 0.0);
            out[OFF_LOSS] = (float)(total * (1.0 / (double)NB));
            g_loss_acc   = 0.0;
            g_done_count = 0u;
        }
    }
}

extern "C" void kernel_launch(void* const* d_in, const int* in_sizes, int n_in,
                              void* d_out, int out_size)
{
    const float* t_bbox = (const float*)d_in[0];
    const float* conf   = (const float*)d_in[1];
    const float* cls    = (const float*)d_in[2];
    const float* gt     = (const float*)d_in[3];
    const int*   gtc    = (const int*)d_in[4];
    const unsigned char* msk = (const unsigned char*)d_in[5];
    float* out = (float*)d_out;

    main_kernel<<<NBLK, 256>>>(t_bbox, conf, cls, gt, gtc, msk, out);
}

// round 7
// speedup vs baseline: 5.0558x; 1.2314x over previous
#include <cuda_runtime.h>
#include <math.h>

#define NB    8
#define NA    3
#define NH    160
#define NW    160
#define NCLS  80
#define NLOC  (NA*NH*NW)          // 76800 per batch
#define NGT   32
#define STRIDE_F 8.0f

#define TILE   128                 // locations per block
#define NBLK   (NB*NLOC/TILE)      // 4800
#define BLK_PER_B (NLOC/TILE)      // 600
#define ROWF4  21                  // float4 per location row (20 + 1 pad)

#define OFF_PBBOX  0
#define OFF_CLSIDX (NB*NLOC*4)
#define OFF_SCORE  (NB*NLOC*4 + NB*NLOC)
#define OFF_LOSS   (NB*NLOC*4 + 2*NB*NLOC)

__device__ double       g_loss_acc;
__device__ unsigned int g_done_count;

__constant__ float c_anchors[9][2] = {
    {10.f,13.f},{16.f,30.f},{33.f,23.f},{30.f,61.f},{62.f,45.f},
    {59.f,119.f},{116.f,90.f},{156.f,198.f},{373.f,326.f}};

__device__ __forceinline__ float sigmoidf_(float x) {
    return __fdividef(1.0f, 1.0f + __expf(-x));
}
__device__ __forceinline__ float bce_(float x, float t) {
    return fmaxf(x, 0.0f) - x * t + log1pf(__expf(-fabsf(x)));
}

// ---------------------------------------------------------------------------
// Single fused kernel. Block = 256 threads -> TILE=128 consecutive locations.
//  P1: cp.async.cg 16B transfers gmem->smem transpose [loc*21 + cg]
//      (no register staging, L1 bypass). t_bbox/conf prefetched before wait.
//  P2: pair mapping h = lane>>4, loc = warp*16 + (lane&15):
//      LDS.128 phase addrs 20*loc mod 32 = {0,20,8,28,16,4,24,12} -> no
//      conflicts. Group-max scan + single re-read for in-group index.
//      Pair combine via shfl_xor(16).
//  P3: decode + IoU vs 16 GTs per half (fast div), shfl_xor(16) max.
//  Block 0 threads also compute 256 per-GT losses.
//  Loss: block reduce -> atomicAdd(double) -> last block writes scalar.
// ---------------------------------------------------------------------------
__global__ __launch_bounds__(256) void main_kernel(
    const float* __restrict__ t_bbox,
    const float* __restrict__ conf,
    const float* __restrict__ cls,
    const float* __restrict__ gt,
    const int*   __restrict__ gt_cls,
    const unsigned char* __restrict__ gt_mask,
    float* __restrict__ out)
{
    __shared__ float4 s_cls[TILE * ROWF4];       // 43008 B
    __shared__ float4 s_gtc[NGT + 2];            // corners, pad g + g/16
    __shared__ float  s_areaB[NGT];
    __shared__ float  s_warp[8];

    const int tid    = threadIdx.x;
    const int blkmod = blockIdx.x % BLK_PER_B;
    const int b      = blockIdx.x / BLK_PER_B;
    const int nbase  = blkmod * TILE;

    // --- GT staging ---
    if (tid < NGT) {
        float4 g = reinterpret_cast<const float4*>(gt)[b * NGT + tid];
        int valid = gt_mask[b * NGT + tid];
        int si = tid + (tid >> 4);
        if (valid) {
            s_gtc[si] = make_float4(g.x - g.z * 0.5f, g.y - g.w * 0.5f,
                                    g.x + g.z * 0.5f, g.y + g.w * 0.5f);
            s_areaB[tid] = g.z * g.w;
        } else {
            s_gtc[si] = make_float4(-3e8f, -3e8f, -3e8f, -3e8f);
            s_areaB[tid] = 0.0f;
        }
    }

    // --- P1: cp.async cls tile (2560 x 16B), transpose [fi + fi/20] ---
    {
        const float4* src = reinterpret_cast<const float4*>(cls)
                          + (b * NLOC + nbase) * 20;
        unsigned sbase = (unsigned)__cvta_generic_to_shared(s_cls);
        #pragma unroll
        for (int k = 0; k < 10; k++) {
            int fi = k * 256 + tid;
            unsigned dst = sbase + (unsigned)(fi + fi / 20) * 16u;
            asm volatile("cp.async.cg.shared.global [%0], [%1], 16;"
                         :: "r"(dst), "l"(src + fi) : "memory");
        }
        asm volatile("cp.async.commit_group;" ::: "memory");
    }

    // pair mapping: h = lane>>4, loc = warp*16 + (lane&15)
    const int lane = tid & 31;
    const int loc  = ((tid >> 5) << 4) + (lane & 15);
    const int h    = lane >> 4;
    const int n    = nbase + loc;
    const int gloc = b * NLOC + n;
    const unsigned FULL = 0xffffffffu;

    // --- prefetch t_bbox/conf while cp.async drains ---
    float4 t = reinterpret_cast<const float4*>(t_bbox)[gloc];
    float conf_logit = conf[gloc];

    asm volatile("cp.async.wait_group 0;" ::: "memory");
    __syncthreads();

    // --- P2: class max/argmax ---
    const int base = loc * ROWF4;
    float gm = -1e30f; int gcg = h;
    {
        #pragma unroll
        for (int k = 0; k < 10; k++) {
            int cg = 2 * k + h;
            float4 v = s_cls[base + cg];
            float m = fmaxf(fmaxf(v.x, v.y), fmaxf(v.z, v.w));
            if (m > gm) { gm = m; gcg = cg; }
        }
    }
    float mv = gm; int mi;
    {
        float4 v = s_cls[base + gcg];
        int r = (v.z == gm) ? 2 : 3;
        if (v.y == gm) r = 1;
        if (v.x == gm) r = 0;
        mi = gcg * 4 + r;
    }
    {
        float ov = __shfl_xor_sync(FULL, mv, 16);
        int   oi = __shfl_xor_sync(FULL, mi, 16);
        if (ov > mv || (ov == mv && oi < mi)) { mv = ov; mi = oi; }
    }

    // --- P3: decode + IoU ---
    const int a   = blkmod / 200;                       // block-uniform
    const int rem = (blkmod % 200) * TILE + loc;        // n % 25600
    const int j   = rem / NW;
    const int i   = rem - j * NW;
    float sx = sigmoidf_(t.x), sy = sigmoidf_(t.y);
    float sw = sigmoidf_(t.z), sh = sigmoidf_(t.w);
    float px = (sx * 2.0f - 0.5f + (float)i) * STRIDE_F;
    float py = (sy * 2.0f - 0.5f + (float)j) * STRIDE_F;
    float tw = sw * 2.0f, th = sh * 2.0f;
    float pw = tw * tw * c_anchors[a][0];
    float ph = th * th * c_anchors[a][1];

    float ax1 = px - pw * 0.5f, ax2 = px + pw * 0.5f;
    float ay1 = py - ph * 0.5f, ay2 = py + ph * 0.5f;
    float areaA = (ax2 - ax1) * (ay2 - ay1);

    float iou = 0.0f;
    #pragma unroll
    for (int k = 0; k < 16; k++) {
        int g = h * 16 + k;
        float4 c = s_gtc[g + (g >> 4)];
        float iw = fmaxf(fminf(ax2, c.z) - fmaxf(ax1, c.x), 0.0f);
        float ih = fmaxf(fminf(ay2, c.w) - fmaxf(ay1, c.y), 0.0f);
        float inter = iw * ih;
        float uni = areaA + s_areaB[g] - inter;
        iou = fmaxf(iou, __fdividef(inter, uni + 1e-16f));
    }
    iou = fmaxf(iou, __shfl_xor_sync(FULL, iou, 16));

    // --- h==0 lanes (0-15 of each warp): coalesced outputs + conf bce ---
    float lsum = 0.0f;
    if (h == 0) {
        lsum = bce_(conf_logit, iou);
        reinterpret_cast<float4*>(out + OFF_PBBOX)[gloc] =
            make_float4(px, py, pw, ph);
        out[OFF_CLSIDX + gloc] = (float)mi;
        out[OFF_SCORE  + gloc] = sigmoidf_(conf_logit) * sigmoidf_(mv);
    }

    // --- block 0 additionally: per-GT losses, one GT per thread ---
    if (blockIdx.x == 0) {
        int gb = tid / NGT;
        int gg = tid % NGT;
        if (gt_mask[gb * NGT + gg]) {
            float4 gbx = reinterpret_cast<const float4*>(gt)[gb * NGT + gg];
            float gw = gbx.z, gh = gbx.w;
            int best = 0; float bestr = -1.0f;
            #pragma unroll
            for (int aa = 0; aa < 9; aa++) {
                float aw = c_anchors[aa][0], ah = c_anchors[aa][1];
                float inter = fminf(gw, aw) * fminf(gh, ah);
                float uni = gw * gh + aw * ah - inter;
                float r = inter / (uni + 1e-16f);
                if (r > bestr) { bestr = r; best = aa; }
            }
            if (best < NA) {
                int ta = best;
                float cxs = gbx.x * (1.0f / STRIDE_F);
                float cys = gbx.y * (1.0f / STRIDE_F);
                int ti = min(max((int)cxs, 0), NW - 1);
                int tj = min(max((int)cys, 0), NH - 1);
                int cell = ((gb * NA + ta) * NH + tj) * NW + ti;
                float4 tb = reinterpret_cast<const float4*>(t_bbox)[cell];
                float tgx = (fmodf(cxs, 1.0f) + 0.5f) * 0.5f;
                float tgy = (fmodf(cys, 1.0f) + 0.5f) * 0.5f;
                float tgw = sqrtf(gw / c_anchors[ta][0]) * 0.5f;
                float tgh = sqrtf(gh / c_anchors[ta][1]) * 0.5f;
                lsum += bce_(tb.x, tgx) + bce_(tb.y, tgy);
                lsum += bce_(tb.z, tgw) + bce_(tb.w, tgh);
                const float* cl = cls + cell * NCLS;
                int tc = gt_cls[gb * NGT + gg];
                float lcls = 0.0f;
                #pragma unroll 8
                for (int c = 0; c < NCLS; c++)
                    lcls += bce_(cl[c], (c == tc) ? 1.0f : 0.0f);
                lsum += lcls * (1.0f / NCLS);
            }
        }
    }

    // --- block reduction -> global double accumulator ---
    #pragma unroll
    for (int off = 16; off; off >>= 1)
        lsum += __shfl_down_sync(FULL, lsum, off);
    if (lane == 0) s_warp[tid >> 5] = lsum;
    __syncthreads();
    if (tid == 0) {
        float s = 0.0f;
        #pragma unroll
        for (int w = 0; w < 8; w++) s += s_warp[w];
        atomicAdd(&g_loss_acc, (double)s);
        __threadfence();
        unsigned int done = atomicAdd(&g_done_count, 1u);
        if (done == NBLK - 1) {
            double total = atomicAdd(&g_loss_acc, 0.0);
            out[OFF_LOSS] = (float)(total * (1.0 / (double)NB));
            g_loss_acc   = 0.0;
            g_done_count = 0u;
        }
    }
}

extern "C" void kernel_launch(void* const* d_in, const int* in_sizes, int n_in,
                              void* d_out, int out_size)
{
    const float* t_bbox = (const float*)d_in[0];
    const float* conf   = (const float*)d_in[1];
    const float* cls    = (const float*)d_in[2];
    const float* gt     = (const float*)d_in[3];
    const int*   gtc    = (const int*)d_in[4];
    const unsigned char* msk = (const unsigned char*)d_in[5];
    float* out = (float*)d_out;

    main_kernel<<<NBLK, 256>>>(t_bbox, conf, cls, gt, gtc, msk, out);
}